// round 1
// baseline (speedup 1.0000x reference)
#include <cuda_runtime.h>
#include <cstdint>

// Problem constants (fixed by the dataset)
#define BB 2
#define SS 2048
#define HH 2048
#define HD 128
#define NH 16
#define MM (BB*SS)   // 4096

// ---------------- scratch (static device globals — no allocation) ----------
__device__ float g_q[(size_t)BB*SS*HH];      // (B,S,H)  Q projection
__device__ float g_k[(size_t)BB*SS*HD];      // (B,S,hd) K projection
__device__ float g_v[(size_t)BB*SS*HD];      // (B,S,hd) V projection
__device__ float g_attn[(size_t)BB*SS*HH];   // (B,S,H)  attention output

// ---------------- fp32 NT GEMM: C[M,N] = A[M,K] @ B[N,K]^T + bias[N] -------
// BM=BN=128, BK=16, 256 threads, 8x8 micro-tile per thread.
#define GBM 128
#define GBN 128
#define GBK 16

__global__ __launch_bounds__(256) void sgemm_nt(
    const float* __restrict__ A, const float* __restrict__ Bw,
    const float* __restrict__ bias, float* __restrict__ C,
    int M, int N, int K)
{
    __shared__ float As[GBK][GBM];
    __shared__ float Bs[GBK][GBN];

    const int tid = threadIdx.x;
    const int tx = tid & 15;        // 0..15 -> col group
    const int ty = tid >> 4;        // 0..15 -> row group
    const int rowBase = blockIdx.y * GBM;
    const int colBase = blockIdx.x * GBN;

    float acc[8][8];
#pragma unroll
    for (int i = 0; i < 8; i++)
#pragma unroll
        for (int j = 0; j < 8; j++) acc[i][j] = 0.f;

    for (int kt = 0; kt < K; kt += GBK) {
        // Load tiles: 128x16 floats each = 512 float4; 2 float4 per thread per tile.
#pragma unroll
        for (int i = 0; i < 2; i++) {
            int idx = tid * 2 + i;           // 0..511
            int r   = idx >> 2;              // 0..127
            int kc  = (idx & 3) * 4;         // 0,4,8,12
            float4 va = *reinterpret_cast<const float4*>(
                &A[(size_t)(rowBase + r) * K + kt + kc]);
            As[kc+0][r] = va.x; As[kc+1][r] = va.y;
            As[kc+2][r] = va.z; As[kc+3][r] = va.w;
            float4 vb = *reinterpret_cast<const float4*>(
                &Bw[(size_t)(colBase + r) * K + kt + kc]);
            Bs[kc+0][r] = vb.x; Bs[kc+1][r] = vb.y;
            Bs[kc+2][r] = vb.z; Bs[kc+3][r] = vb.w;
        }
        __syncthreads();

#pragma unroll
        for (int k = 0; k < GBK; k++) {
            float ra[8], rb[8];
            float4 a0 = *reinterpret_cast<const float4*>(&As[k][ty*8]);
            float4 a1 = *reinterpret_cast<const float4*>(&As[k][ty*8+4]);
            ra[0]=a0.x; ra[1]=a0.y; ra[2]=a0.z; ra[3]=a0.w;
            ra[4]=a1.x; ra[5]=a1.y; ra[6]=a1.z; ra[7]=a1.w;
            float4 b0 = *reinterpret_cast<const float4*>(&Bs[k][tx*8]);
            float4 b1 = *reinterpret_cast<const float4*>(&Bs[k][tx*8+4]);
            rb[0]=b0.x; rb[1]=b0.y; rb[2]=b0.z; rb[3]=b0.w;
            rb[4]=b1.x; rb[5]=b1.y; rb[6]=b1.z; rb[7]=b1.w;
#pragma unroll
            for (int i = 0; i < 8; i++)
#pragma unroll
                for (int j = 0; j < 8; j++)
                    acc[i][j] = fmaf(ra[i], rb[j], acc[i][j]);
        }
        __syncthreads();
    }

    // Epilogue: add bias, write C (all dims divide evenly — no guards needed)
#pragma unroll
    for (int i = 0; i < 8; i++) {
        size_t rowOff = (size_t)(rowBase + ty*8 + i) * N + colBase + tx*8;
#pragma unroll
        for (int j = 0; j < 8; j++)
            C[rowOff + j] = acc[i][j] + bias[colBase + tx*8 + j];
    }
}

// ---------------- flash-style MQA attention --------------------------------
// grid: (S/64, NH, B), block: 256 threads.
// Q tile 64x128 resident; stream K/V tiles of 64 rows; online softmax.
#define AQ 64
#define AKB 64
#define QSTR 129    // padded row stride for Q/K/V smem tiles
#define PSTR 65     // padded row stride for score tile

#define ATTN_SMEM_FLOATS (3*AQ*QSTR + AQ*PSTR + 3*AQ)
#define ATTN_SMEM_BYTES  (ATTN_SMEM_FLOATS * 4)

__global__ __launch_bounds__(256) void mqa_attn(
    const float* __restrict__ q, const float* __restrict__ k,
    const float* __restrict__ v, const int* __restrict__ mask,
    float* __restrict__ out)
{
    extern __shared__ float sm[];
    float* Qs = sm;                       // 64 x 129
    float* Ks = Qs + AQ*QSTR;             // 64 x 129
    float* Vs = Ks + AQ*QSTR;             // 64 x 129
    float* Ps = Vs + AQ*QSTR;             // 64 x 65
    float* Ms = Ps + AQ*PSTR;             // 64
    float* Ls = Ms + AQ;                  // 64
    float* Cs = Ls + AQ;                  // 64

    const int tid = threadIdx.x;
    const int qb = blockIdx.x;
    const int h  = blockIdx.y;
    const int b  = blockIdx.z;
    const int tx = tid & 15;              // 0..15
    const int tg = tid >> 4;              // 0..15
    const int r0 = tg * 4;                // 4 score/out rows per thread
    const int c0 = tx * 4;                // 4 score cols per thread
    const int cv0 = tx * 8;               // 8 out cols per thread

    // Load Q tile (rows qb*64.., cols h*128..) — 2048 float4, 8 per thread.
#pragma unroll
    for (int i = 0; i < 8; i++) {
        int idx = tid + i*256;            // 0..2047
        int r  = idx >> 5;                // 0..63
        int d  = (idx & 31) * 4;
        float4 vq = *reinterpret_cast<const float4*>(
            &q[((size_t)(b*SS + qb*AQ + r)) * HH + h*HD + d]);
        Qs[r*QSTR + d+0] = vq.x; Qs[r*QSTR + d+1] = vq.y;
        Qs[r*QSTR + d+2] = vq.z; Qs[r*QSTR + d+3] = vq.w;
    }
    if (tid < AQ) { Ms[tid] = -1e30f; Ls[tid] = 0.f; }

    float acc[4][8];
#pragma unroll
    for (int i = 0; i < 4; i++)
#pragma unroll
        for (int j = 0; j < 8; j++) acc[i][j] = 0.f;

    const float scale = 0.08838834764831845f;   // 1/sqrt(128)

    for (int kb = 0; kb < SS/AKB; kb++) {
        // Load K and V tiles
#pragma unroll
        for (int i = 0; i < 8; i++) {
            int idx = tid + i*256;
            int r  = idx >> 5;
            int d  = (idx & 31) * 4;
            size_t goff = ((size_t)(b*SS + kb*AKB + r)) * HD + d;
            float4 vk = *reinterpret_cast<const float4*>(&k[goff]);
            Ks[r*QSTR + d+0] = vk.x; Ks[r*QSTR + d+1] = vk.y;
            Ks[r*QSTR + d+2] = vk.z; Ks[r*QSTR + d+3] = vk.w;
            float4 vv = *reinterpret_cast<const float4*>(&v[goff]);
            Vs[r*QSTR + d+0] = vv.x; Vs[r*QSTR + d+1] = vv.y;
            Vs[r*QSTR + d+2] = vv.z; Vs[r*QSTR + d+3] = vv.w;
        }
        __syncthreads();

        // Scores: 4x4 per thread over hd=128
        float sc[4][4];
#pragma unroll
        for (int i = 0; i < 4; i++)
#pragma unroll
            for (int j = 0; j < 4; j++) sc[i][j] = 0.f;

#pragma unroll 8
        for (int d = 0; d < HD; d++) {
            float ra[4], rk[4];
#pragma unroll
            for (int i = 0; i < 4; i++) ra[i] = Qs[(r0+i)*QSTR + d];
#pragma unroll
            for (int j = 0; j < 4; j++) rk[j] = Ks[(c0+j)*QSTR + d];
#pragma unroll
            for (int i = 0; i < 4; i++)
#pragma unroll
                for (int j = 0; j < 4; j++)
                    sc[i][j] = fmaf(ra[i], rk[j], sc[i][j]);
        }

        // Scale + mask, write to score tile
#pragma unroll
        for (int j = 0; j < 4; j++) {
            int mv = mask[b*SS + kb*AKB + c0 + j];
#pragma unroll
            for (int i = 0; i < 4; i++) {
                float val = sc[i][j] * scale;
                if (mv == 0) val = -1e30f;
                Ps[(r0+i)*PSTR + c0 + j] = val;
            }
        }
        __syncthreads();

        // Online softmax: one thread per row
        if (tid < AQ) {
            int r = tid;
            float mx = -1e30f;
#pragma unroll 8
            for (int j = 0; j < AKB; j++) mx = fmaxf(mx, Ps[r*PSTR + j]);
            float mold = Ms[r];
            float mnew = fmaxf(mold, mx);
            float corr = __expf(mold - mnew);
            float sum = 0.f;
#pragma unroll 8
            for (int j = 0; j < AKB; j++) {
                float e = __expf(Ps[r*PSTR + j] - mnew);
                Ps[r*PSTR + j] = e;
                sum += e;
            }
            Ls[r] = Ls[r] * corr + sum;
            Ms[r] = mnew;
            Cs[r] = corr;
        }
        __syncthreads();

        // Rescale accumulators and accumulate P @ V
        float cr[4];
#pragma unroll
        for (int i = 0; i < 4; i++) cr[i] = Cs[r0+i];
#pragma unroll
        for (int i = 0; i < 4; i++)
#pragma unroll
            for (int j = 0; j < 8; j++) acc[i][j] *= cr[i];

#pragma unroll 4
        for (int j = 0; j < AKB; j++) {
            float rp[4], rv[8];
#pragma unroll
            for (int i = 0; i < 4; i++) rp[i] = Ps[(r0+i)*PSTR + j];
#pragma unroll
            for (int j2 = 0; j2 < 8; j2++) rv[j2] = Vs[j*QSTR + cv0 + j2];
#pragma unroll
            for (int i = 0; i < 4; i++)
#pragma unroll
                for (int j2 = 0; j2 < 8; j2++)
                    acc[i][j2] = fmaf(rp[i], rv[j2], acc[i][j2]);
        }
        __syncthreads();   // before overwriting K/V tiles
    }

    // Final normalize + write (B,S,H) with head offset (transpose fused)
#pragma unroll
    for (int i = 0; i < 4; i++) {
        float inv = 1.0f / Ls[r0+i];
        size_t o = ((size_t)(b*SS + qb*AQ + r0 + i)) * HH + h*HD + cv0;
#pragma unroll
        for (int j2 = 0; j2 < 8; j2++)
            out[o + j2] = acc[i][j2] * inv;
    }
}

// ---------------- launch ---------------------------------------------------
extern "C" void kernel_launch(void* const* d_in, const int* in_sizes, int n_in,
                              void* d_out, int out_size)
{
    const float* hidden = (const float*)d_in[0];
    const int*   mask   = (const int*)  d_in[1];
    const float* Wq = (const float*)d_in[2];
    const float* bq = (const float*)d_in[3];
    const float* Wk = (const float*)d_in[4];
    const float* bk = (const float*)d_in[5];
    const float* Wv = (const float*)d_in[6];
    const float* bv = (const float*)d_in[7];
    const float* Wo = (const float*)d_in[8];
    const float* bo = (const float*)d_in[9];
    float* out = (float*)d_out;

    float *q, *k, *v, *attn;
    cudaGetSymbolAddress((void**)&q,    g_q);
    cudaGetSymbolAddress((void**)&k,    g_k);
    cudaGetSymbolAddress((void**)&v,    g_v);
    cudaGetSymbolAddress((void**)&attn, g_attn);

    cudaFuncSetAttribute(mqa_attn, cudaFuncAttributeMaxDynamicSharedMemorySize,
                         ATTN_SMEM_BYTES);

    // Q projection: (4096,2048) = hidden @ Wq^T + bq
    sgemm_nt<<<dim3(HH/GBN, MM/GBM), 256>>>(hidden, Wq, bq, q, MM, HH, HH);
    // K/V projections: (4096,128)
    sgemm_nt<<<dim3(1, MM/GBM), 256>>>(hidden, Wk, bk, k, MM, HD, HH);
    sgemm_nt<<<dim3(1, MM/GBM), 256>>>(hidden, Wv, bv, v, MM, HD, HH);
    // Attention
    mqa_attn<<<dim3(SS/AQ, NH, BB), 256, ATTN_SMEM_BYTES>>>(q, k, v, mask, attn);
    // Output projection
    sgemm_nt<<<dim3(HH/GBN, MM/GBM), 256>>>(attn, Wo, bo, out, MM, HH, HH);
}